// round 15
// baseline (speedup 1.0000x reference)
#include <cuda_runtime.h>
#include <cuda_fp16.h>
#include <cstdint>

// ============================================================
// Fused GRUCell, sm_103 base-PTX (ldmatrix + mma.sync.m16n8k16).
// R14 kernel (permuted layout + pipelined B-fragment loads) with
// all activations vectorized via tanh.approx.f16x2: one MUFU op
// per TWO values, sigmoid = 0.5*tanh(0.5x)+0.5 in half2, epilogue
// blend in half2 (HFMA2). Halves MUFU work and shortens the
// serial non-tensor phases that cap issue at 2 warps/SMSP.
//   r = sig(x@Wir + hx@Whr + br); z = sig(x@Wiz + hx@Whz + bz)
//   n = tanh(x@Win + (r*hx)@Whn + bn); h = hx + z*(n - hx)
// B = 1048576, H = 64. M = 32 rows per warp per iteration.
// ============================================================

#define DEV __device__ __forceinline__

static constexpr int NSLAB = 1048576 / 32;       // 32768 slabs of 32 rows

// ---- dynamic SMEM layout (bytes) ----
static constexpr int OFF_W    = 0;               // 6 x [64x64] f16 SW128 rows = 49152
static constexpr int OFF_BIAS = 49152;           // 3 x 64 fp32 = 768
static constexpr int SMEM_SZ  = 50176;

DEV uint32_t sw(uint32_t o) { return o ^ ((o >> 3) & 0x70); }

DEV uint32_t s2u(const void* p) {
    uint32_t a;
    asm("{ .reg .u64 t; cvta.to.shared.u64 t, %1; cvt.u32.u64 %0, t; }" : "=r"(a) : "l"(p));
    return a;
}

DEV void pf_l2(const void* p) {
    asm volatile("prefetch.global.L2 [%0];" :: "l"(p));
}

DEV void ldsm4t(uint32_t& d0, uint32_t& d1, uint32_t& d2, uint32_t& d3, uint32_t a) {
    asm volatile("ldmatrix.sync.aligned.m8n8.x4.trans.shared.b16 {%0,%1,%2,%3}, [%4];"
                 : "=r"(d0), "=r"(d1), "=r"(d2), "=r"(d3) : "r"(a));
}

DEV void mma4(float* c, const uint32_t* a, uint32_t b0, uint32_t b1) {
    asm volatile(
        "mma.sync.aligned.m16n8k16.row.col.f32.f16.f16.f32 "
        "{%0,%1,%2,%3}, {%4,%5,%6,%7}, {%8,%9}, {%0,%1,%2,%3};"
        : "+f"(c[0]), "+f"(c[1]), "+f"(c[2]), "+f"(c[3])
        : "r"(a[0]), "r"(a[1]), "r"(a[2]), "r"(a[3]), "r"(b0), "r"(b1));
}

DEV uint32_t packh2(float a, float b) {
    __half2 h = __floats2half2_rn(a, b);
    return *(uint32_t*)&h;
}

// ---- f16x2 activations (1 MUFU per 2 values) ----
DEV __half2 tanh2h(uint32_t v) {
    uint32_t r;
    asm("tanh.approx.f16x2 %0, %1;" : "=r"(r) : "r"(v));
    return *(__half2*)&r;
}
DEV __half2 sigm2h(uint32_t v) {
    const __half2 h05 = __half2half2(__ushort_as_half(0x3800));   // 0.5
    __half2 x = __hmul2(*(__half2*)&v, h05);
    uint32_t r;
    asm("tanh.approx.f16x2 %0, %1;" : "=r"(r) : "r"(*(uint32_t*)&x));
    return __hfma2(*(__half2*)&r, h05, h05);
}

// B-fragment smem address for step i (kb = i>>2, nbp = i&3)
DEV uint32_t baddr(uint32_t wb, int i, int laneB) {
    return wb + sw((uint32_t)(laneB + (i >> 2) * 2048 + (i & 3) * 32));
}

// One gate: acc += A0(32x64) @ W0 + A1(32x64) @ W1, B-fragment loads
// software-pipelined (next ldsm issued before current MMA group).
DEV void gemm_gate(float acc[2][8][4],
                   const uint32_t af0[2][4][4], const uint32_t af1[2][4][4],
                   uint32_t wb0, uint32_t wb1, int laneB) {
    uint32_t b0[4], b1[4];
    ldsm4t(b0[0], b0[1], b0[2], b0[3], baddr(wb0, 0, laneB));
    #pragma unroll
    for (int i = 0; i < 16; i++) {
        uint32_t* bc = (i & 1) ? b1 : b0;
        uint32_t* bn = (i & 1) ? b0 : b1;
        if (i < 15) ldsm4t(bn[0], bn[1], bn[2], bn[3], baddr(wb0, i + 1, laneB));
        else        ldsm4t(bn[0], bn[1], bn[2], bn[3], baddr(wb1, 0, laneB));
        const int kb = i >> 2, nbp = i & 3;
        #pragma unroll
        for (int mb = 0; mb < 2; mb++) {
            mma4(acc[mb][2 * nbp],     af0[mb][kb], bc[0], bc[1]);
            mma4(acc[mb][2 * nbp + 1], af0[mb][kb], bc[2], bc[3]);
        }
    }
    #pragma unroll
    for (int i = 0; i < 16; i++) {
        uint32_t* bc = (i & 1) ? b1 : b0;
        uint32_t* bn = (i & 1) ? b0 : b1;
        if (i < 15) ldsm4t(bn[0], bn[1], bn[2], bn[3], baddr(wb1, i + 1, laneB));
        const int kb = i >> 2, nbp = i & 3;
        #pragma unroll
        for (int mb = 0; mb < 2; mb++) {
            mma4(acc[mb][2 * nbp],     af1[mb][kb], bc[0], bc[1]);
            mma4(acc[mb][2 * nbp + 1], af1[mb][kb], bc[2], bc[3]);
        }
    }
}

__global__ void __launch_bounds__(256, 1) gru_kernel(
    const float* __restrict__ x,    const float* __restrict__ hx,
    const float* __restrict__ w_ir, const float* __restrict__ w_hr,
    const float* __restrict__ w_iz, const float* __restrict__ w_hz,
    const float* __restrict__ w_in, const float* __restrict__ w_hn,
    const float* __restrict__ b_r,  const float* __restrict__ b_z,
    const float* __restrict__ b_n,  float* __restrict__ out)
{
    extern __shared__ char sm[];
    const uint32_t SB = s2u(sm);
    const int tid  = threadIdx.x;
    const int lane = tid & 31;
    const int wid  = tid >> 5;

    // ---- one-time: weights -> f16 SMEM, K-rows and N-cols permuted ----
    // K row perm (per 16-block):  krow(k) = 2*((k>>2)&3) + (k&1) + ((k&2)<<2)
    // N col perm sigma^-1 (per 16-block): pos(n) = ((n&2)<<2) | ((n>>1)&6) | (n&1)
    {
        const float* ws[6] = {w_ir, w_hr, w_iz, w_hz, w_in, w_hn};
        #pragma unroll 1
        for (int g = 0; g < 6; g++) {
            const float* w = ws[g];
            for (int i = tid; i < 4096; i += 256) {
                int k = i >> 6, n = i & 63;
                int krow = (k & 48) | (2 * ((k >> 2) & 3) + (k & 1) + ((k & 2) << 2));
                int ncol = (n & 48) | ((n & 2) << 2) | ((n >> 1) & 6) | (n & 1);
                *(__half*)(sm + OFF_W + g * 8192 + sw((uint32_t)(krow * 128 + ncol * 2))) =
                    __float2half_rn(w[i]);
            }
        }
        if (tid < 64) {
            // bias position j holds b[sigma(j)]
            int m = ((tid >> 4) << 4) | ((tid & 6) << 1) | (((tid >> 3) & 1) << 1) | (tid & 1);
            float* bs = (float*)(sm + OFF_BIAS);
            bs[tid]       = b_r[m];
            bs[64 + tid]  = b_z[m];
            bs[128 + tid] = b_n[m];
        }
    }
    __syncthreads();   // only CTA-wide barrier in the kernel

    const int laneB = (lane & 15) * 128 + ((lane >> 4) << 4);  // ldmatrix B lane offset
    const int q2    = (lane & 3) * 2;
    const int t4    = (lane & 3) * 4;
    const int grow  = lane >> 2;

    const long stride = 8L * gridDim.x;

    for (long g = (long)blockIdx.x * 8 + wid; g < NSLAB; g += stride) {
        // ---- L2 prefetch of next slab ----
        {
            const long gp = g + stride;
            if (gp < NSLAB) {
                const char* px = (const char*)(x  + (size_t)gp * 2048) + lane * 256;
                const char* ph = (const char*)(hx + (size_t)gp * 2048) + lane * 256;
                pf_l2(px); pf_l2(px + 128);
                pf_l2(ph); pf_l2(ph + 128);
            }
        }

        // ---- A-fragments via LDG.128 (permuted K space) ----
        uint32_t xf[2][4][4], hf[2][4][4];
        {
            const float* xb = x  + (size_t)g * 2048;   // 32 rows x 64
            const float* hb = hx + (size_t)g * 2048;
            #pragma unroll
            for (int mb = 0; mb < 2; mb++) {
                const float* xr = xb + (mb * 16 + grow) * 64 + t4;
                const float* hr = hb + (mb * 16 + grow) * 64 + t4;
                #pragma unroll
                for (int kb = 0; kb < 4; kb++) {
                    float4 q0 = *(const float4*)(xr + kb * 16);
                    float4 q8 = *(const float4*)(xr + kb * 16 + 512);   // +8 rows
                    xf[mb][kb][0] = packh2(q0.x, q0.y);
                    xf[mb][kb][2] = packh2(q0.z, q0.w);
                    xf[mb][kb][1] = packh2(q8.x, q8.y);
                    xf[mb][kb][3] = packh2(q8.z, q8.w);
                    float4 p0 = *(const float4*)(hr + kb * 16);
                    float4 p8 = *(const float4*)(hr + kb * 16 + 512);
                    hf[mb][kb][0] = packh2(p0.x, p0.y);
                    hf[mb][kb][2] = packh2(p0.z, p0.w);
                    hf[mb][kb][1] = packh2(p8.x, p8.y);
                    hf[mb][kb][3] = packh2(p8.z, p8.w);
                }
            }
        }

        // ---- r = sig(x@Wir + hx@Whr + br) ----
        float rc[2][8][4];
        #pragma unroll
        for (int nb = 0; nb < 8; nb++) {
            float2 br = *(float2*)(sm + OFF_BIAS + (nb * 8 + q2) * 4);
            #pragma unroll
            for (int mb = 0; mb < 2; mb++) {
                rc[mb][nb][0] = br.x; rc[mb][nb][1] = br.y;
                rc[mb][nb][2] = br.x; rc[mb][nb][3] = br.y;
            }
        }
        gemm_gate(rc, xf, hf, SB + OFF_W, SB + OFF_W + 1 * 8192, laneB);

        // ---- rh = sigmoid(rc) * hx -> A-fragments (f16x2 sigmoid; rc dies) ----
        uint32_t rhf[2][4][4];
        #pragma unroll
        for (int mb = 0; mb < 2; mb++) {
            #pragma unroll
            for (int kb = 0; kb < 4; kb++) {
                const float* ce = rc[mb][2 * kb];
                const float* co = rc[mb][2 * kb + 1];
                __half2 s0 = sigm2h(packh2(ce[0], ce[1]));
                __half2 s1 = sigm2h(packh2(ce[2], ce[3]));
                __half2 s2 = sigm2h(packh2(co[0], co[1]));
                __half2 s3 = sigm2h(packh2(co[2], co[3]));
                __half2 m0 = __hmul2(s0, *(const __half2*)&hf[mb][kb][0]);
                __half2 m1 = __hmul2(s1, *(const __half2*)&hf[mb][kb][1]);
                __half2 m2 = __hmul2(s2, *(const __half2*)&hf[mb][kb][2]);
                __half2 m3 = __hmul2(s3, *(const __half2*)&hf[mb][kb][3]);
                rhf[mb][kb][0] = *(uint32_t*)&m0;
                rhf[mb][kb][1] = *(uint32_t*)&m1;
                rhf[mb][kb][2] = *(uint32_t*)&m2;
                rhf[mb][kb][3] = *(uint32_t*)&m3;
            }
        }

        // ---- n = x@Win + rh@Whn + bn ----
        float nc[2][8][4];
        #pragma unroll
        for (int nb = 0; nb < 8; nb++) {
            float2 bn = *(float2*)(sm + OFF_BIAS + 512 + (nb * 8 + q2) * 4);
            #pragma unroll
            for (int mb = 0; mb < 2; mb++) {
                nc[mb][nb][0] = bn.x; nc[mb][nb][1] = bn.y;
                nc[mb][nb][2] = bn.x; nc[mb][nb][3] = bn.y;
            }
        }
        gemm_gate(nc, xf, rhf, SB + OFF_W + 4 * 8192, SB + OFF_W + 5 * 8192, laneB);

        // ---- z = sig(x@Wiz + hx@Whz + bz) (rhf dead) ----
        float zc[2][8][4];
        #pragma unroll
        for (int nb = 0; nb < 8; nb++) {
            float2 bz = *(float2*)(sm + OFF_BIAS + 256 + (nb * 8 + q2) * 4);
            #pragma unroll
            for (int mb = 0; mb < 2; mb++) {
                zc[mb][nb][0] = bz.x; zc[mb][nb][1] = bz.y;
                zc[mb][nb][2] = bz.x; zc[mb][nb][3] = bz.y;
            }
        }
        gemm_gate(zc, xf, hf, SB + OFF_W + 2 * 8192, SB + OFF_W + 3 * 8192, laneB);

        // ---- epilogue: h = hx + z*(n - hx), all-half2 (HFMA2) ----
        #pragma unroll
        for (int mb = 0; mb < 2; mb++) {
            const long rg = g * 32 + mb * 16 + grow;
            #pragma unroll
            for (int kb = 0; kb < 4; kb++) {
                const float* ze = zc[mb][2 * kb];
                const float* zo = zc[mb][2 * kb + 1];
                const float* ne = nc[mb][2 * kb];
                const float* no = nc[mb][2 * kb + 1];
                __half2 z01 = sigm2h(packh2(ze[0], ze[1]));   // row grow,   cols 0,1
                __half2 z23 = sigm2h(packh2(zo[0], zo[1]));   // row grow,   cols 2,3
                __half2 z81 = sigm2h(packh2(ze[2], ze[3]));   // row grow+8, cols 0,1
                __half2 z83 = sigm2h(packh2(zo[2], zo[3]));   // row grow+8, cols 2,3
                __half2 n01 = tanh2h(packh2(ne[0], ne[1]));
                __half2 n23 = tanh2h(packh2(no[0], no[1]));
                __half2 n81 = tanh2h(packh2(ne[2], ne[3]));
                __half2 n83 = tanh2h(packh2(no[2], no[3]));
                __half2 h01 = *(const __half2*)&hf[mb][kb][0];
                __half2 h23 = *(const __half2*)&hf[mb][kb][2];
                __half2 h81 = *(const __half2*)&hf[mb][kb][1];
                __half2 h83 = *(const __half2*)&hf[mb][kb][3];
                __half2 o01 = __hfma2(z01, __hsub2(n01, h01), h01);
                __half2 o23 = __hfma2(z23, __hsub2(n23, h23), h23);
                __half2 o81 = __hfma2(z81, __hsub2(n81, h81), h81);
                __half2 o83 = __hfma2(z83, __hsub2(n83, h83), h83);
                float2 f01 = __half22float2(o01), f23 = __half22float2(o23);
                float2 f81 = __half22float2(o81), f83 = __half22float2(o83);
                *(float4*)(out + rg * 64 + kb * 16 + t4) =
                    make_float4(f01.x, f01.y, f23.x, f23.y);
                *(float4*)(out + (rg + 8) * 64 + kb * 16 + t4) =
                    make_float4(f81.x, f81.y, f83.x, f83.y);
            }
        }
    }
}

extern "C" void kernel_launch(void* const* d_in, const int* in_sizes, int n_in,
                              void* d_out, int out_size) {
    int sms = 0;
    cudaDeviceGetAttribute(&sms, cudaDevAttrMultiProcessorCount, 0);
    if (sms <= 0) sms = 148;
    cudaFuncSetAttribute(gru_kernel, cudaFuncAttributeMaxDynamicSharedMemorySize, SMEM_SZ);
    gru_kernel<<<sms, 256, SMEM_SZ>>>(
        (const float*)d_in[0], (const float*)d_in[1],
        (const float*)d_in[2], (const float*)d_in[3],
        (const float*)d_in[4], (const float*)d_in[5],
        (const float*)d_in[6], (const float*)d_in[7],
        (const float*)d_in[8], (const float*)d_in[9],
        (const float*)d_in[10], (float*)d_out);
}

// round 16
// speedup vs baseline: 1.0174x; 1.0174x over previous
#include <cuda_runtime.h>
#include <cuda_fp16.h>
#include <cstdint>

// ============================================================
// Fused GRUCell, sm_103 base-PTX (ldmatrix + mma.sync.m16n8k16).
// R14 kernel + fused r/z dual-gate GEMM with fp16 accumulators:
// f16-C fragments (2 regs) halve r/z accumulator liveness, so the
// r and z chains interleave per MMA step (2x ILP in the largest
// GEMM phase) without the R12 spill cliff. The f16 C-fragment is
// directly the half2 (row, col-pair) shape needed by rhf and the
// epilogue's z. n keeps fp32 accumulation; epilogue blend fp32.
//   r = sig(x@Wir + hx@Whr + br); z = sig(x@Wiz + hx@Whz + bz)
//   n = tanh(x@Win + (r*hx)@Whn + bn); h = hx + z*(n - hx)
// B = 1048576, H = 64. M = 32 rows per warp per iteration.
// ============================================================

#define DEV __device__ __forceinline__

static constexpr int NSLAB = 1048576 / 32;       // 32768 slabs of 32 rows

// ---- dynamic SMEM layout (bytes) ----
static constexpr int OFF_W    = 0;               // 6 x [64x64] f16 SW128 rows = 49152
static constexpr int OFF_BIAS = 49152;           // 3 x 64 fp32 = 768
static constexpr int SMEM_SZ  = 50176;

DEV uint32_t sw(uint32_t o) { return o ^ ((o >> 3) & 0x70); }

DEV uint32_t s2u(const void* p) {
    uint32_t a;
    asm("{ .reg .u64 t; cvta.to.shared.u64 t, %1; cvt.u32.u64 %0, t; }" : "=r"(a) : "l"(p));
    return a;
}

DEV void pf_l2(const void* p) {
    asm volatile("prefetch.global.L2 [%0];" :: "l"(p));
}

DEV void ldsm4t(uint32_t& d0, uint32_t& d1, uint32_t& d2, uint32_t& d3, uint32_t a) {
    asm volatile("ldmatrix.sync.aligned.m8n8.x4.trans.shared.b16 {%0,%1,%2,%3}, [%4];"
                 : "=r"(d0), "=r"(d1), "=r"(d2), "=r"(d3) : "r"(a));
}

// fp32-accumulate mma (for n)
DEV void mma4(float* c, const uint32_t* a, uint32_t b0, uint32_t b1) {
    asm volatile(
        "mma.sync.aligned.m16n8k16.row.col.f32.f16.f16.f32 "
        "{%0,%1,%2,%3}, {%4,%5,%6,%7}, {%8,%9}, {%0,%1,%2,%3};"
        : "+f"(c[0]), "+f"(c[1]), "+f"(c[2]), "+f"(c[3])
        : "r"(a[0]), "r"(a[1]), "r"(a[2]), "r"(a[3]), "r"(b0), "r"(b1));
}

// fp16-accumulate mma (for r, z): C/D = 2 regs of half2
DEV void mma2h(uint32_t* c, const uint32_t* a, uint32_t b0, uint32_t b1) {
    asm volatile(
        "mma.sync.aligned.m16n8k16.row.col.f16.f16.f16.f16 "
        "{%0,%1}, {%2,%3,%4,%5}, {%6,%7}, {%0,%1};"
        : "+r"(c[0]), "+r"(c[1])
        : "r"(a[0]), "r"(a[1]), "r"(a[2]), "r"(a[3]), "r"(b0), "r"(b1));
}

// activations
DEV float tanh_ap(float x) {
    float r;
    asm("tanh.approx.f32 %0, %1;" : "=f"(r) : "f"(x));
    return r;
}
DEV __half2 sigm2h(uint32_t v) {
    const __half2 h05 = __half2half2(__ushort_as_half(0x3800));   // 0.5
    __half2 x = __hmul2(*(__half2*)&v, h05);
    uint32_t r;
    asm("tanh.approx.f16x2 %0, %1;" : "=r"(r) : "r"(*(uint32_t*)&x));
    return __hfma2(*(__half2*)&r, h05, h05);
}

DEV uint32_t packh2(float a, float b) {
    __half2 h = __floats2half2_rn(a, b);
    return *(uint32_t*)&h;
}

// B-fragment smem address for step i (kb = i>>2, nbp = i&3)
DEV uint32_t baddr(uint32_t wb, int i, int laneB) {
    return wb + sw((uint32_t)(laneB + (i >> 2) * 2048 + (i & 3) * 32));
}

// Fused r/z gate: r16 += A@Wr, z16 += A@Wz over (x then hx) parts,
// B loads for both gates pipelined one step ahead.
DEV void gate_rz(uint32_t r16[2][8][2], uint32_t z16[2][8][2],
                 const uint32_t af0[2][4][4], const uint32_t af1[2][4][4],
                 uint32_t wbr0, uint32_t wbr1, uint32_t wbz0, uint32_t wbz1,
                 int laneB) {
    uint32_t bra[4], brb[4], bza[4], bzb[4];
    ldsm4t(bra[0], bra[1], bra[2], bra[3], baddr(wbr0, 0, laneB));
    ldsm4t(bza[0], bza[1], bza[2], bza[3], baddr(wbz0, 0, laneB));
    #pragma unroll
    for (int i = 0; i < 32; i++) {
        uint32_t* brc = (i & 1) ? brb : bra;
        uint32_t* brn = (i & 1) ? bra : brb;
        uint32_t* bzc = (i & 1) ? bzb : bza;
        uint32_t* bzn = (i & 1) ? bza : bzb;
        if (i < 31) {
            int j = i + 1;
            uint32_t wr = (j < 16) ? wbr0 : wbr1;
            uint32_t wz = (j < 16) ? wbz0 : wbz1;
            ldsm4t(brn[0], brn[1], brn[2], brn[3], baddr(wr, j & 15, laneB));
            ldsm4t(bzn[0], bzn[1], bzn[2], bzn[3], baddr(wz, j & 15, laneB));
        }
        const int kb = (i & 15) >> 2, nbp = i & 3;
        const uint32_t (*af)[4][4] = (i < 16) ? af0 : af1;
        #pragma unroll
        for (int mb = 0; mb < 2; mb++) {
            mma2h(r16[mb][2 * nbp],     af[mb][kb], brc[0], brc[1]);
            mma2h(r16[mb][2 * nbp + 1], af[mb][kb], brc[2], brc[3]);
            mma2h(z16[mb][2 * nbp],     af[mb][kb], bzc[0], bzc[1]);
            mma2h(z16[mb][2 * nbp + 1], af[mb][kb], bzc[2], bzc[3]);
        }
    }
}

// fp32 gate for n (R14's pipelined version)
DEV void gemm_gate(float acc[2][8][4],
                   const uint32_t af0[2][4][4], const uint32_t af1[2][4][4],
                   uint32_t wb0, uint32_t wb1, int laneB) {
    uint32_t b0[4], b1[4];
    ldsm4t(b0[0], b0[1], b0[2], b0[3], baddr(wb0, 0, laneB));
    #pragma unroll
    for (int i = 0; i < 32; i++) {
        uint32_t* bc = (i & 1) ? b1 : b0;
        uint32_t* bn = (i & 1) ? b0 : b1;
        if (i < 31) {
            int j = i + 1;
            uint32_t wb = (j < 16) ? wb0 : wb1;
            ldsm4t(bn[0], bn[1], bn[2], bn[3], baddr(wb, j & 15, laneB));
        }
        const int kb = (i & 15) >> 2, nbp = i & 3;
        const uint32_t (*af)[4][4] = (i < 16) ? af0 : af1;
        #pragma unroll
        for (int mb = 0; mb < 2; mb++) {
            mma4(acc[mb][2 * nbp],     af[mb][kb], bc[0], bc[1]);
            mma4(acc[mb][2 * nbp + 1], af[mb][kb], bc[2], bc[3]);
        }
    }
}

__global__ void __launch_bounds__(256, 1) gru_kernel(
    const float* __restrict__ x,    const float* __restrict__ hx,
    const float* __restrict__ w_ir, const float* __restrict__ w_hr,
    const float* __restrict__ w_iz, const float* __restrict__ w_hz,
    const float* __restrict__ w_in, const float* __restrict__ w_hn,
    const float* __restrict__ b_r,  const float* __restrict__ b_z,
    const float* __restrict__ b_n,  float* __restrict__ out)
{
    extern __shared__ char sm[];
    const uint32_t SB = s2u(sm);
    const int tid  = threadIdx.x;
    const int lane = tid & 31;
    const int wid  = tid >> 5;

    // ---- one-time: weights -> f16 SMEM, K-rows and N-cols permuted ----
    // K row perm (per 16-block):  krow(k) = 2*((k>>2)&3) + (k&1) + ((k&2)<<2)
    // N col perm sigma^-1 (per 16-block): pos(n) = ((n&2)<<2) | ((n>>1)&6) | (n&1)
    {
        const float* ws[6] = {w_ir, w_hr, w_iz, w_hz, w_in, w_hn};
        #pragma unroll 1
        for (int g = 0; g < 6; g++) {
            const float* w = ws[g];
            for (int i = tid; i < 4096; i += 256) {
                int k = i >> 6, n = i & 63;
                int krow = (k & 48) | (2 * ((k >> 2) & 3) + (k & 1) + ((k & 2) << 2));
                int ncol = (n & 48) | ((n & 2) << 2) | ((n >> 1) & 6) | (n & 1);
                *(__half*)(sm + OFF_W + g * 8192 + sw((uint32_t)(krow * 128 + ncol * 2))) =
                    __float2half_rn(w[i]);
            }
        }
        if (tid < 64) {
            // bias position j holds b[sigma(j)]
            int m = ((tid >> 4) << 4) | ((tid & 6) << 1) | (((tid >> 3) & 1) << 1) | (tid & 1);
            float* bs = (float*)(sm + OFF_BIAS);
            bs[tid]       = b_r[m];
            bs[64 + tid]  = b_z[m];
            bs[128 + tid] = b_n[m];
        }
    }
    __syncthreads();   // only CTA-wide barrier in the kernel

    const int laneB = (lane & 15) * 128 + ((lane >> 4) << 4);  // ldmatrix B lane offset
    const int q2    = (lane & 3) * 2;
    const int t4    = (lane & 3) * 4;
    const int grow  = lane >> 2;

    const long stride = 8L * gridDim.x;

    for (long g = (long)blockIdx.x * 8 + wid; g < NSLAB; g += stride) {
        // ---- L2 prefetch of next slab ----
        {
            const long gp = g + stride;
            if (gp < NSLAB) {
                const char* px = (const char*)(x  + (size_t)gp * 2048) + lane * 256;
                const char* ph = (const char*)(hx + (size_t)gp * 2048) + lane * 256;
                pf_l2(px); pf_l2(px + 128);
                pf_l2(ph); pf_l2(ph + 128);
            }
        }

        // ---- A-fragments via LDG.128 (permuted K space) ----
        uint32_t xf[2][4][4], hf[2][4][4];
        {
            const float* xb = x  + (size_t)g * 2048;   // 32 rows x 64
            const float* hb = hx + (size_t)g * 2048;
            #pragma unroll
            for (int mb = 0; mb < 2; mb++) {
                const float* xr = xb + (mb * 16 + grow) * 64 + t4;
                const float* hr = hb + (mb * 16 + grow) * 64 + t4;
                #pragma unroll
                for (int kb = 0; kb < 4; kb++) {
                    float4 q0 = *(const float4*)(xr + kb * 16);
                    float4 q8 = *(const float4*)(xr + kb * 16 + 512);   // +8 rows
                    xf[mb][kb][0] = packh2(q0.x, q0.y);
                    xf[mb][kb][2] = packh2(q0.z, q0.w);
                    xf[mb][kb][1] = packh2(q8.x, q8.y);
                    xf[mb][kb][3] = packh2(q8.z, q8.w);
                    float4 p0 = *(const float4*)(hr + kb * 16);
                    float4 p8 = *(const float4*)(hr + kb * 16 + 512);
                    hf[mb][kb][0] = packh2(p0.x, p0.y);
                    hf[mb][kb][2] = packh2(p0.z, p0.w);
                    hf[mb][kb][1] = packh2(p8.x, p8.y);
                    hf[mb][kb][3] = packh2(p8.z, p8.w);
                }
            }
        }

        // ---- fused r & z (fp16 accumulators, bias-initialized) ----
        // r16[mb][nb][0] = half2 (row grow,  cols pair nb); [1] = row grow+8
        uint32_t r16[2][8][2], z16[2][8][2];
        #pragma unroll
        for (int nb = 0; nb < 8; nb++) {
            float2 br = *(float2*)(sm + OFF_BIAS       + (nb * 8 + q2) * 4);
            float2 bz = *(float2*)(sm + OFF_BIAS + 256 + (nb * 8 + q2) * 4);
            uint32_t brh = packh2(br.x, br.y);
            uint32_t bzh = packh2(bz.x, bz.y);
            #pragma unroll
            for (int mb = 0; mb < 2; mb++) {
                r16[mb][nb][0] = brh; r16[mb][nb][1] = brh;
                z16[mb][nb][0] = bzh; z16[mb][nb][1] = bzh;
            }
        }
        gate_rz(r16, z16, xf, hf,
                SB + OFF_W,            SB + OFF_W + 1 * 8192,
                SB + OFF_W + 2 * 8192, SB + OFF_W + 3 * 8192, laneB);

        // ---- rhf = sigmoid(r) * hx: f16 C-frag is already the right half2 ----
        uint32_t rhf[2][4][4];
        #pragma unroll
        for (int mb = 0; mb < 2; mb++) {
            #pragma unroll
            for (int kb = 0; kb < 4; kb++) {
                __half2 m0 = __hmul2(sigm2h(r16[mb][2 * kb][0]),     *(const __half2*)&hf[mb][kb][0]);
                __half2 m1 = __hmul2(sigm2h(r16[mb][2 * kb][1]),     *(const __half2*)&hf[mb][kb][1]);
                __half2 m2 = __hmul2(sigm2h(r16[mb][2 * kb + 1][0]), *(const __half2*)&hf[mb][kb][2]);
                __half2 m3 = __hmul2(sigm2h(r16[mb][2 * kb + 1][1]), *(const __half2*)&hf[mb][kb][3]);
                rhf[mb][kb][0] = *(uint32_t*)&m0;
                rhf[mb][kb][1] = *(uint32_t*)&m1;
                rhf[mb][kb][2] = *(uint32_t*)&m2;
                rhf[mb][kb][3] = *(uint32_t*)&m3;
            }
        }

        // ---- n = x@Win + rh@Whn + bn (fp32 accumulate) ----
        float nc[2][8][4];
        #pragma unroll
        for (int nb = 0; nb < 8; nb++) {
            float2 bn = *(float2*)(sm + OFF_BIAS + 512 + (nb * 8 + q2) * 4);
            #pragma unroll
            for (int mb = 0; mb < 2; mb++) {
                nc[mb][nb][0] = bn.x; nc[mb][nb][1] = bn.y;
                nc[mb][nb][2] = bn.x; nc[mb][nb][3] = bn.y;
            }
        }
        gemm_gate(nc, xf, rhf, SB + OFF_W + 4 * 8192, SB + OFF_W + 5 * 8192, laneB);

        // ---- epilogue: h = hx + z*(n - hx); z from f16 frags, fp32 blend ----
        #pragma unroll
        for (int mb = 0; mb < 2; mb++) {
            const long rg = g * 32 + mb * 16 + grow;
            #pragma unroll
            for (int kb = 0; kb < 4; kb++) {
                float2 h01 = __half22float2(*(const __half2*)&hf[mb][kb][0]); // row grow
                float2 h23 = __half22float2(*(const __half2*)&hf[mb][kb][2]);
                float2 g01 = __half22float2(*(const __half2*)&hf[mb][kb][1]); // row grow+8
                float2 g23 = __half22float2(*(const __half2*)&hf[mb][kb][3]);
                float2 z01 = __half22float2(sigm2h(z16[mb][2 * kb][0]));
                float2 z23 = __half22float2(sigm2h(z16[mb][2 * kb + 1][0]));
                float2 z81 = __half22float2(sigm2h(z16[mb][2 * kb][1]));
                float2 z83 = __half22float2(sigm2h(z16[mb][2 * kb + 1][1]));
                const float* ne = nc[mb][2 * kb];
                const float* no = nc[mb][2 * kb + 1];
                float4 o0, o8;
                o0.x = fmaf(z01.x, tanh_ap(ne[0]) - h01.x, h01.x);
                o0.y = fmaf(z01.y, tanh_ap(ne[1]) - h01.y, h01.y);
                o0.z = fmaf(z23.x, tanh_ap(no[0]) - h23.x, h23.x);
                o0.w = fmaf(z23.y, tanh_ap(no[1]) - h23.y, h23.y);
                o8.x = fmaf(z81.x, tanh_ap(ne[2]) - g01.x, g01.x);
                o8.y = fmaf(z81.y, tanh_ap(ne[3]) - g01.y, g01.y);
                o8.z = fmaf(z83.x, tanh_ap(no[2]) - g23.x, g23.x);
                o8.w = fmaf(z83.y, tanh_ap(no[3]) - g23.y, g23.y);
                *(float4*)(out + rg * 64 + kb * 16 + t4)       = o0;
                *(float4*)(out + (rg + 8) * 64 + kb * 16 + t4) = o8;
            }
        }
    }
}

extern "C" void kernel_launch(void* const* d_in, const int* in_sizes, int n_in,
                              void* d_out, int out_size) {
    int sms = 0;
    cudaDeviceGetAttribute(&sms, cudaDevAttrMultiProcessorCount, 0);
    if (sms <= 0) sms = 148;
    cudaFuncSetAttribute(gru_kernel, cudaFuncAttributeMaxDynamicSharedMemorySize, SMEM_SZ);
    gru_kernel<<<sms, 256, SMEM_SZ>>>(
        (const float*)d_in[0], (const float*)d_in[1],
        (const float*)d_in[2], (const float*)d_in[3],
        (const float*)d_in[4], (const float*)d_in[5],
        (const float*)d_in[6], (const float*)d_in[7],
        (const float*)d_in[8], (const float*)d_in[9],
        (const float*)d_in[10], (float*)d_out);
}